// round 5
// baseline (speedup 1.0000x reference)
#include <cuda_runtime.h>
#include <cuda_fp16.h>

#define NN 50000
#define NE 800000

// Scratch (device globals — no allocation allowed in kernel_launch).
// g_Z4: per-node Z padded to 384B (24 float4, 3 full 128B lines): float4
// index f=2d+h holds fp16 Z[d][h*8..h*8+7], d=0..7 from nnW, d=8 from nnb;
// f=18..23 unused padding.
__device__ alignas(128) float4 g_Z4[(size_t)NN * 24];
__device__ float g_agg[2][(size_t)NN * 16];  // ping-pong node feature buffers

// ---------------------------------------------------------------------------
// prep: per node n, Z[n][d][o] = sum_i x[n][i] * W[d][i*16+o] (d=8 uses nnb),
// stored fp16 (384B padded stride); agg_out[n] = x[n] @ rootW + bias (fp32).
// ---------------------------------------------------------------------------
__global__ void __launch_bounds__(128) prep_kernel(
    const float* __restrict__ x0, int layer,
    const float* __restrict__ nnW, const float* __restrict__ nnb,
    const float* __restrict__ rootW, const float* __restrict__ bias)
{
    __shared__ float4 sWB[576];   // [0,512): nnW (8 x 256 floats), [512,576): nnb
    __shared__ float4 sR[64];     // rootW
    __shared__ float4 sBias[4];   // bias

    const int tid = threadIdx.x;
    const float4* W4  = (const float4*)(nnW   + (size_t)layer * 2048);
    const float4* B4  = (const float4*)(nnb   + (size_t)layer * 256);
    const float4* R4  = (const float4*)(rootW + (size_t)layer * 256);
    const float4* Bi4 = (const float4*)(bias  + (size_t)layer * 16);

    #pragma unroll
    for (int j = tid; j < 512; j += 128) sWB[j] = W4[j];
    for (int j = tid; j < 64;  j += 128) { sWB[512 + j] = B4[j]; sR[j] = R4[j]; }
    if (tid < 4) sBias[tid] = Bi4[tid];
    __syncthreads();

    const int n = blockIdx.x * 128 + tid;
    if (n >= NN) return;

    const float* xin = (layer == 0) ? x0 : g_agg[(layer - 1) & 1];

    float x[16];
    const float4* xr = (const float4*)(xin + (size_t)n * 16);
    #pragma unroll
    for (int c = 0; c < 4; c++) {
        float4 v = xr[c];
        x[4*c+0] = v.x; x[4*c+1] = v.y; x[4*c+2] = v.z; x[4*c+3] = v.w;
    }
    if (layer) {
        #pragma unroll
        for (int i = 0; i < 16; i++) x[i] = fmaxf(x[i], 0.f);
    }

    float4* Zo = g_Z4 + (size_t)n * 24;
    #pragma unroll 1
    for (int d = 0; d < 9; d++) {
        const float4* Wd = sWB + d * 64;
        float4 acc[4];
        #pragma unroll
        for (int oc = 0; oc < 4; oc++) {
            float4 a = make_float4(0.f, 0.f, 0.f, 0.f);
            #pragma unroll
            for (int i = 0; i < 16; i++) {
                float4 w = Wd[i * 4 + oc];
                a.x = fmaf(x[i], w.x, a.x);
                a.y = fmaf(x[i], w.y, a.y);
                a.z = fmaf(x[i], w.z, a.z);
                a.w = fmaf(x[i], w.w, a.w);
            }
            acc[oc] = a;
        }
        __half2 h[8];
        #pragma unroll
        for (int oc = 0; oc < 4; oc++) {
            h[2*oc+0] = __floats2half2_rn(acc[oc].x, acc[oc].y);
            h[2*oc+1] = __floats2half2_rn(acc[oc].z, acc[oc].w);
        }
        Zo[d * 2 + 0] = *(float4*)&h[0];
        Zo[d * 2 + 1] = *(float4*)&h[4];
    }

    // root term: agg_out[n] = x @ rootW + bias
    float4* Ao = (float4*)(g_agg[layer & 1] + (size_t)n * 16);
    #pragma unroll
    for (int oc = 0; oc < 4; oc++) {
        float4 acc = sBias[oc];
        #pragma unroll
        for (int i = 0; i < 16; i++) {
            float4 w = sR[i * 4 + oc];
            acc.x = fmaf(x[i], w.x, acc.x);
            acc.y = fmaf(x[i], w.y, acc.y);
            acc.z = fmaf(x[i], w.z, acc.z);
            acc.w = fmaf(x[i], w.w, acc.w);
        }
        Ao[oc] = acc;
    }
}

// ---------------------------------------------------------------------------
// edge: 8 threads per edge, whole-line cooperative loads (3 L1 wavefronts of
// Z per edge). Thread q loads f = q (d=q>>1), f = 8+q (d=4+(q>>1)), half
// h = q&1; q<2 also load f=16+q (nnb row, half q). 2-step fp16 HFMA2, then
// fp32: nnb seed, xor-2 + xor-4 butterfly reduce; threads q<4 each RED.128
// one output quarter.
// ---------------------------------------------------------------------------
__global__ void __launch_bounds__(256) edge_kernel(
    const int* __restrict__ ei, const float* __restrict__ ea, int layer)
{
    __shared__ __half2 s_c[32 * 9 + 4];  // [edge][d] broadcast pairs, stride 9
    __shared__ int     s_src[32];
    __shared__ int     s_dst[32];

    const int tid = threadIdx.x;
    const int e0  = blockIdx.x * 32;

    {   // 32 edges x 8 dims = 256 floats, one per thread
        float v = ea[(size_t)e0 * 8 + tid];
        s_c[(tid >> 3) * 9 + (tid & 7)] = __float2half2_rn(v);
    }
    if (tid < 32)      s_src[tid]      = ei[e0 + tid];
    else if (tid < 64) s_dst[tid - 32] = ei[NE + e0 + (tid - 32)];
    __syncthreads();

    const int le  = tid >> 3;
    const int q   = tid & 7;
    const int h   = q & 1;
    const int src = s_src[le];
    const int dst = s_dst[le];

    const float4* zp = g_Z4 + (size_t)src * 24 + q;
    float4 v0 = __ldcg(zp);       // f = q     : d = q>>1
    float4 v1 = __ldcg(zp + 8);   // f = 8+q   : d = 4+(q>>1)

    const __half2* cb = s_c + le * 9 + (q >> 1);
    const __half2 c0 = cb[0];
    const __half2 c1 = cb[4];

    const __half2* h0 = (const __half2*)&v0;
    const __half2* h1 = (const __half2*)&v1;
    float m[8];
    #pragma unroll
    for (int j = 0; j < 4; j++) {
        __half2 a = __hfma2(c1, h1[j], __hmul2(c0, h0[j]));
        float2 t = __half22float2(a);
        m[2*j] = t.x; m[2*j+1] = t.y;
    }

    if (q < 2) {  // nnb term (d=8, coefficient 1), added in fp32
        float4 vb = __ldcg(zp + 16);
        const __half2* hb = (const __half2*)&vb;
        #pragma unroll
        for (int j = 0; j < 4; j++) {
            float2 t = __half22float2(hb[j]);
            m[2*j] += t.x; m[2*j+1] += t.y;
        }
    }

    // Round 1 (xor 2): partner has same h, adjacent d-pair. q&2==0 keeps
    // outputs h*8+[0,4), q&2 keeps h*8+[4,8).
    const int keepHi = (q & 2) ? 4 : 0;
    float r[4];
    #pragma unroll
    for (int i = 0; i < 4; i++) {
        float send = m[(4 - keepHi) + i];
        float recv = __shfl_xor_sync(0xffffffffu, send, 2);
        r[i] = m[keepHi + i] + recv;
    }
    // Round 2 (xor 4): partner covers the remaining d's of the same quarter.
    #pragma unroll
    for (int i = 0; i < 4; i++)
        r[i] += __shfl_xor_sync(0xffffffffu, r[i], 4);

    if (q < 4) {
        float* ag = g_agg[layer & 1] + (size_t)dst * 16 + h * 8 + keepHi;
        asm volatile("red.global.add.v4.f32 [%0], {%1,%2,%3,%4};"
                     :: "l"(ag), "f"(r[0]), "f"(r[1]), "f"(r[2]), "f"(r[3]) : "memory");
    }
}

// ---------------------------------------------------------------------------
// head: out[n] = relu(agg[n]) . head_W[0:16] + gf[:,n] . head_W[16:24] + head_b
// ---------------------------------------------------------------------------
__global__ void __launch_bounds__(256) head_kernel(
    const float* __restrict__ gf, const float* __restrict__ hW,
    const float* __restrict__ hb, float* __restrict__ out)
{
    const int n = blockIdx.x * 256 + threadIdx.x;
    if (n >= NN) return;

    const float4* ar = (const float4*)(g_agg[0] + (size_t)n * 16);  // layer 2 wrote buf 0
    float acc = hb[0];
    #pragma unroll
    for (int c = 0; c < 4; c++) {
        float4 v = ar[c];
        acc = fmaf(fmaxf(v.x, 0.f), hW[4*c+0], acc);
        acc = fmaf(fmaxf(v.y, 0.f), hW[4*c+1], acc);
        acc = fmaf(fmaxf(v.z, 0.f), hW[4*c+2], acc);
        acc = fmaf(fmaxf(v.w, 0.f), hW[4*c+3], acc);
    }
    #pragma unroll
    for (int g = 0; g < 8; g++)
        acc = fmaf(gf[(size_t)g * NN + n], hW[16 + g], acc);
    out[n] = acc;
}

extern "C" void kernel_launch(void* const* d_in, const int* in_sizes, int n_in,
                              void* d_out, int out_size)
{
    const float* x     = (const float*)d_in[0];
    const int*   ei    = (const int*)  d_in[1];
    const float* ea    = (const float*)d_in[2];
    const float* gf    = (const float*)d_in[3];
    const float* nnW   = (const float*)d_in[4];
    const float* nnb   = (const float*)d_in[5];
    const float* rootW = (const float*)d_in[6];
    const float* bias  = (const float*)d_in[7];
    const float* hW    = (const float*)d_in[8];
    const float* hb    = (const float*)d_in[9];
    float* out = (float*)d_out;

    for (int layer = 0; layer < 3; layer++) {
        prep_kernel<<<(NN + 127) / 128, 128>>>(x, layer, nnW, nnb, rootW, bias);
        edge_kernel<<<NE / 32, 256>>>(ei, ea, layer);
    }
    head_kernel<<<(NN + 255) / 256, 256>>>(gf, hW, hb, out);
}

// round 6
// speedup vs baseline: 1.1066x; 1.1066x over previous
#include <cuda_runtime.h>
#include <cuda_fp16.h>

#define NN 50000
#define NE 800000

// Scratch (device globals — no allocation allowed in kernel_launch).
// g_Z4: per-node Z padded to 320B (20 float4): float4 index f=2d+h holds fp16
// Z[d][h*8..h*8+7], d=0..7 from nnW, d=8 from nnb; f=18,19 unused padding.
__device__ float4 g_Z4[(size_t)NN * 20];
__device__ float  g_agg[2][(size_t)NN * 16];  // ping-pong node feature buffers
// Packed per-edge data (built once per launch by pack_kernel):
// g_pc[2e+hi] = 4 pre-broadcast half2 coefficients {c,c} for d = hi,2+hi,4+hi,6+hi
__device__ float4 g_pc[(size_t)NE * 2];
__device__ int2   g_idx[(size_t)NE];          // (src, dst)

// ---------------------------------------------------------------------------
// pack: one-time conversion of edge_attr -> pre-broadcast fp16 coefficient
// groups + packed (src,dst). Removes all per-layer staging from edge_kernel.
// ---------------------------------------------------------------------------
__global__ void __launch_bounds__(256) pack_kernel(
    const int* __restrict__ ei, const float* __restrict__ ea)
{
    const int e = blockIdx.x * 256 + threadIdx.x;
    if (e >= NE) return;
    const float4 a = ((const float4*)ea)[(size_t)e * 2 + 0];  // c0..c3
    const float4 b = ((const float4*)ea)[(size_t)e * 2 + 1];  // c4..c7

    __half2 h0[4] = { __float2half2_rn(a.x), __float2half2_rn(a.z),
                      __float2half2_rn(b.x), __float2half2_rn(b.z) };  // hi=0: c0,c2,c4,c6
    __half2 h1[4] = { __float2half2_rn(a.y), __float2half2_rn(a.w),
                      __float2half2_rn(b.y), __float2half2_rn(b.w) };  // hi=1: c1,c3,c5,c7
    g_pc[(size_t)e * 2 + 0] = *(float4*)h0;
    g_pc[(size_t)e * 2 + 1] = *(float4*)h1;
    g_idx[e] = make_int2(ei[e], ei[NE + e]);
}

// ---------------------------------------------------------------------------
// prep: per node n, Z[n][d][o] = sum_i x[n][i] * W[d][i*16+o] (d=8 uses nnb),
// stored fp16 (320B padded stride); agg_out[n] = x[n] @ rootW + bias (fp32).
// ---------------------------------------------------------------------------
__global__ void __launch_bounds__(128) prep_kernel(
    const float* __restrict__ x0, int layer,
    const float* __restrict__ nnW, const float* __restrict__ nnb,
    const float* __restrict__ rootW, const float* __restrict__ bias)
{
    __shared__ float4 sWB[576];   // [0,512): nnW (8 x 256 floats), [512,576): nnb
    __shared__ float4 sR[64];     // rootW
    __shared__ float4 sBias[4];   // bias

    const int tid = threadIdx.x;
    const float4* W4  = (const float4*)(nnW   + (size_t)layer * 2048);
    const float4* B4  = (const float4*)(nnb   + (size_t)layer * 256);
    const float4* R4  = (const float4*)(rootW + (size_t)layer * 256);
    const float4* Bi4 = (const float4*)(bias  + (size_t)layer * 16);

    #pragma unroll
    for (int j = tid; j < 512; j += 128) sWB[j] = W4[j];
    for (int j = tid; j < 64;  j += 128) { sWB[512 + j] = B4[j]; sR[j] = R4[j]; }
    if (tid < 4) sBias[tid] = Bi4[tid];
    __syncthreads();

    const int n = blockIdx.x * 128 + tid;
    if (n >= NN) return;

    const float* xin = (layer == 0) ? x0 : g_agg[(layer - 1) & 1];

    float x[16];
    const float4* xr = (const float4*)(xin + (size_t)n * 16);
    #pragma unroll
    for (int c = 0; c < 4; c++) {
        float4 v = xr[c];
        x[4*c+0] = v.x; x[4*c+1] = v.y; x[4*c+2] = v.z; x[4*c+3] = v.w;
    }
    if (layer) {
        #pragma unroll
        for (int i = 0; i < 16; i++) x[i] = fmaxf(x[i], 0.f);
    }

    float4* Zo = g_Z4 + (size_t)n * 20;
    #pragma unroll 1
    for (int d = 0; d < 9; d++) {
        const float4* Wd = sWB + d * 64;
        float4 acc[4];
        #pragma unroll
        for (int oc = 0; oc < 4; oc++) {
            float4 a = make_float4(0.f, 0.f, 0.f, 0.f);
            #pragma unroll
            for (int i = 0; i < 16; i++) {
                float4 w = Wd[i * 4 + oc];
                a.x = fmaf(x[i], w.x, a.x);
                a.y = fmaf(x[i], w.y, a.y);
                a.z = fmaf(x[i], w.z, a.z);
                a.w = fmaf(x[i], w.w, a.w);
            }
            acc[oc] = a;
        }
        __half2 h[8];
        #pragma unroll
        for (int oc = 0; oc < 4; oc++) {
            h[2*oc+0] = __floats2half2_rn(acc[oc].x, acc[oc].y);
            h[2*oc+1] = __floats2half2_rn(acc[oc].z, acc[oc].w);
        }
        Zo[d * 2 + 0] = *(float4*)&h[0];
        Zo[d * 2 + 1] = *(float4*)&h[4];
    }

    // root term: agg_out[n] = x @ rootW + bias
    float4* Ao = (float4*)(g_agg[layer & 1] + (size_t)n * 16);
    #pragma unroll
    for (int oc = 0; oc < 4; oc++) {
        float4 acc = sBias[oc];
        #pragma unroll
        for (int i = 0; i < 16; i++) {
            float4 w = sR[i * 4 + oc];
            acc.x = fmaf(x[i], w.x, acc.x);
            acc.y = fmaf(x[i], w.y, acc.y);
            acc.z = fmaf(x[i], w.z, acc.z);
            acc.w = fmaf(x[i], w.w, acc.w);
        }
        Ao[oc] = acc;
    }
}

// ---------------------------------------------------------------------------
// edge: 4 threads per edge, NO shared memory, no __syncthreads.
//   Thread q loads float4 f = {q, 4+q, 8+q, 12+q} (+16+q if q<2):
//   d = (q>>1) + {0,2,4,6}, output half h = q&1.
//   Coefficients come pre-broadcast from g_pc[2e + (q>>1)] (one LDG.128).
//   Math: two 2-term HFMA2 chains combined in fp32; nnb added in fp32.
//   xor-2 shfl reduce; one red.v4.f32 per thread.
// ---------------------------------------------------------------------------
__global__ void __launch_bounds__(256) edge_kernel(int layer)
{
    const int gid = blockIdx.x * 256 + threadIdx.x;
    const int e   = gid >> 2;
    const int q   = gid & 3;
    const int hi  = q >> 1;

    const int2 sd = g_idx[e];
    const float4 cpack = g_pc[(size_t)e * 2 + hi];
    const __half2* cp = (const __half2*)&cpack;
    const __half2 c0 = cp[0], c1 = cp[1], c2 = cp[2], c3 = cp[3];

    const float4* zp = g_Z4 + (size_t)sd.x * 20 + q;
    float4 v0 = __ldcg(zp + 0);    // d = hi
    float4 v1 = __ldcg(zp + 4);    // d = 2+hi
    float4 v2 = __ldcg(zp + 8);    // d = 4+hi
    float4 v3 = __ldcg(zp + 12);   // d = 6+hi

    const __half2* h0 = (const __half2*)&v0;
    const __half2* h1 = (const __half2*)&v1;
    const __half2* h2 = (const __half2*)&v2;
    const __half2* h3 = (const __half2*)&v3;

    float m[8];
    #pragma unroll
    for (int j = 0; j < 4; j++) {
        __half2 t1 = __hfma2(c1, h1[j], __hmul2(c0, h0[j]));
        __half2 t2 = __hfma2(c3, h3[j], __hmul2(c2, h2[j]));
        float2 f1 = __half22float2(t1);
        float2 f2 = __half22float2(t2);
        m[2*j]   = f1.x + f2.x;
        m[2*j+1] = f1.y + f2.y;
    }

    if (q < 2) {  // nnb term (d=8, coefficient 1), added in fp32
        float4 vb = __ldcg(zp + 16);
        const __half2* hb = (const __half2*)&vb;
        #pragma unroll
        for (int j = 0; j < 4; j++) {
            float2 t = __half22float2(hb[j]);
            m[2*j] += t.x; m[2*j+1] += t.y;
        }
    }

    // Cross-pair reduction (q <-> q^2: same output half q&1, other d's).
    // hi==0 keeps m[0..3] (sends m[4..7]); hi==1 keeps m[4..7].
    float r[4];
    #pragma unroll
    for (int i = 0; i < 4; i++) {
        float send = hi ? m[i] : m[4 + i];
        float recv = __shfl_xor_sync(0xffffffffu, send, 2);
        r[i] = m[hi * 4 + i] + recv;
    }

    float* ag = g_agg[layer & 1] + (size_t)sd.y * 16 + (q & 1) * 8 + hi * 4;
    asm volatile("red.global.add.v4.f32 [%0], {%1,%2,%3,%4};"
                 :: "l"(ag), "f"(r[0]), "f"(r[1]), "f"(r[2]), "f"(r[3]) : "memory");
}

// ---------------------------------------------------------------------------
// head: out[n] = relu(agg[n]) . head_W[0:16] + gf[:,n] . head_W[16:24] + head_b
// ---------------------------------------------------------------------------
__global__ void __launch_bounds__(256) head_kernel(
    const float* __restrict__ gf, const float* __restrict__ hW,
    const float* __restrict__ hb, float* __restrict__ out)
{
    const int n = blockIdx.x * 256 + threadIdx.x;
    if (n >= NN) return;

    const float4* ar = (const float4*)(g_agg[0] + (size_t)n * 16);  // layer 2 wrote buf 0
    float acc = hb[0];
    #pragma unroll
    for (int c = 0; c < 4; c++) {
        float4 v = ar[c];
        acc = fmaf(fmaxf(v.x, 0.f), hW[4*c+0], acc);
        acc = fmaf(fmaxf(v.y, 0.f), hW[4*c+1], acc);
        acc = fmaf(fmaxf(v.z, 0.f), hW[4*c+2], acc);
        acc = fmaf(fmaxf(v.w, 0.f), hW[4*c+3], acc);
    }
    #pragma unroll
    for (int g = 0; g < 8; g++)
        acc = fmaf(gf[(size_t)g * NN + n], hW[16 + g], acc);
    out[n] = acc;
}

extern "C" void kernel_launch(void* const* d_in, const int* in_sizes, int n_in,
                              void* d_out, int out_size)
{
    const float* x     = (const float*)d_in[0];
    const int*   ei    = (const int*)  d_in[1];
    const float* ea    = (const float*)d_in[2];
    const float* gf    = (const float*)d_in[3];
    const float* nnW   = (const float*)d_in[4];
    const float* nnb   = (const float*)d_in[5];
    const float* rootW = (const float*)d_in[6];
    const float* bias  = (const float*)d_in[7];
    const float* hW    = (const float*)d_in[8];
    const float* hb    = (const float*)d_in[9];
    float* out = (float*)d_out;

    pack_kernel<<<(NE + 255) / 256, 256>>>(ei, ea);
    for (int layer = 0; layer < 3; layer++) {
        prep_kernel<<<(NN + 127) / 128, 128>>>(x, layer, nnW, nnb, rootW, bias);
        edge_kernel<<<NE * 4 / 256, 256>>>(layer);
    }
    head_kernel<<<(NN + 255) / 256, 256>>>(gf, hW, hb, out);
}